// round 12
// baseline (speedup 1.0000x reference)
#include <cuda_runtime.h>
#include <cuda_bf16.h>
#include <math.h>

// ---------------- problem constants ----------------
// B=16, L=128, D=512, E=512, DI=2048, T=127, V=32000

// ---------------- scratch (device globals), R7 layouts ----------------
__device__ float d_emb  [2048*512];     // row m = l*16+b
__device__ float d_xgf  [2048*2048];    // [m=t*16+b][2048]
__device__ float d_xgb  [2048*2048];
__device__ float d_xenc [16*128*1024];  // [b][l][2D]
__device__ float d_xenck[16*128*512];   // [b][l][D]
__device__ float d_hf[2][16*512];       // [b][512]
__device__ float d_hb[2][16*512];
__device__ float d_cf[16*512];          // [b][512]
__device__ float d_cb[16*512];
__device__ float d_biasF[2048];
__device__ float d_biasB[2048];
__device__ float d_attr [16*512];
__device__ float d_abase[16*2048];      // [b][n]
__device__ float d_gbase[2032*2048];    // [m=t*16+b][2048]
__device__ float d_hdec[2][16*512];     // [b][512]
__device__ float d_cdec[16*512];        // [b][512]
__device__ float d_feed [16*1024];      // [b][1024]
__device__ float d_attq [16*512];
__device__ float d_sraw [16*128];
__device__ float d_hcall[2032*1536];    // [m][h512, ctx1024]
__device__ float d_pres [2032*512];

// ---------------- software grid barrier (replay-safe) ----------------
__device__ unsigned g_count = 0;
__device__ unsigned g_gen   = 0;

__device__ __forceinline__ void gbar(unsigned nb){
    __syncthreads();
    if (threadIdx.x == 0){
        __threadfence();
        unsigned gen = atomicAdd(&g_gen, 0u);
        if (atomicAdd(&g_count, 1u) == nb - 1u){
            atomicExch(&g_count, 0u);
            __threadfence();
            atomicAdd(&g_gen, 1u);
        } else {
            while (atomicAdd(&g_gen, 0u) == gen) __nanosleep(32);
        }
        __threadfence();
    }
    __syncthreads();
}

// ---------------- math helpers ----------------
__device__ __forceinline__ float tanha(float x){            // accurate
    x = fminf(fmaxf(x, -15.f), 15.f);
    float e = __expf(2.f * x);
    return __fdividef(e - 1.f, e + 1.f);
}
__device__ __forceinline__ float sigm(float x){
    return __fdividef(1.f, 1.f + __expf(-x));
}
__device__ __forceinline__ float tanhx(float x){            // HW approx (scores only)
    float y; asm("tanh.approx.f32 %0, %1;" : "=f"(y) : "f"(x)); return y;
}
#define DOT4(a,x,w) (a) += (x).x*(w).x + (x).y*(w).y + (x).z*(w).z + (x).w*(w).w

// ---------------- prep kernels (R7) ----------------
__global__ void k_init(){
    int i = blockIdx.x*256 + threadIdx.x;
    if (i < 16*512){ d_hf[0][i]=0.f; d_hb[0][i]=0.f; d_cf[i]=0.f; d_cb[i]=0.f; }
    if (i < 16*1024) d_feed[i]=0.f;
}

__global__ void k_bias(const float* __restrict__ bihf, const float* __restrict__ bhhf,
                       const float* __restrict__ bihb, const float* __restrict__ bhhb){
    int i = blockIdx.x*256 + threadIdx.x;
    if (i < 2048){ d_biasF[i] = bihf[i] + bhhf[i]; d_biasB[i] = bihb[i] + bhhb[i]; }
}

__global__ void k_embed(const int* __restrict__ x_train, const float* __restrict__ word_emb){
    int m = blockIdx.x;                 // m = l*16+b
    int b = m & 15, l = m >> 4;
    int tok = x_train[b*128 + l];
    const float4* src = (const float4*)(word_emb + (size_t)tok*512);
    float4* dst = (float4*)(d_emb + (size_t)m*512);
    dst[threadIdx.x] = src[threadIdx.x];
}

__global__ void k_attr(const int* __restrict__ y_train, const float* __restrict__ attr_emb){
    int b = blockIdx.x;
    float4 s = make_float4(0.f,0.f,0.f,0.f);
    for (int j = 0; j < 2; j++){
        int tok = y_train[b*2 + j];
        float4 v = ((const float4*)(attr_emb + (size_t)tok*512))[threadIdx.x];
        s.x += v.x; s.y += v.y; s.z += v.z; s.w += v.w;
    }
    ((float4*)(d_attr + b*512))[threadIdx.x] = s;
}

__global__ void k_abase(const float* __restrict__ Wih_d,
                        const float* __restrict__ bih_d, const float* __restrict__ bhh_d){
    int p = blockIdx.x*128 + threadIdx.x;     // 32768
    int b = p & 15, n = p >> 4;
    const float4* xp = (const float4*)(d_attr + b*512);
    const float4* wp = (const float4*)(Wih_d + (size_t)n*2048 + 512);
    float acc = 0.f;
    #pragma unroll 8
    for (int k = 0; k < 128; k++){ float4 x = xp[k], w = wp[k]; DOT4(acc,x,w); }
    d_abase[b*2048 + n] = acc + bih_d[n] + bhh_d[n];
}

// ---------------- generic SGEMM (exact R7): C[m][n] = sum_k A[m][k]*B[n][k] ----------------
__global__ __launch_bounds__(256) void k_gemm(
    const float* __restrict__ A, int lda,
    const float* __restrict__ B, int ldb,
    float* __restrict__ C, int ldc,
    int M, int K,
    const float* __restrict__ bias,
    const float* __restrict__ bias2d,
    int act, int mode)
{
    __shared__ float As[2][8][132];
    __shared__ float Bs[2][8][132];
    const int tid = threadIdx.x;
    const int m0 = blockIdx.y * 128, n0 = blockIdx.x * 128;
    const int lm = tid >> 1, lk4 = (tid & 1) * 4;
    const bool mval = (m0 + lm) < M;
    const float* Ap = A + (size_t)(m0 + lm) * lda + lk4;
    const float* Bp = B + (size_t)(n0 + lm) * ldb + lk4;
    const int tx = tid & 15, ty = tid >> 4;

    float cr[8][8];
    #pragma unroll
    for (int i = 0; i < 8; i++)
        #pragma unroll
        for (int j = 0; j < 8; j++) cr[i][j] = 0.f;

    float4 av = mval ? *(const float4*)Ap : make_float4(0,0,0,0);
    float4 bv = *(const float4*)Bp;
    As[0][lk4+0][lm]=av.x; As[0][lk4+1][lm]=av.y; As[0][lk4+2][lm]=av.z; As[0][lk4+3][lm]=av.w;
    Bs[0][lk4+0][lm]=bv.x; Bs[0][lk4+1][lm]=bv.y; Bs[0][lk4+2][lm]=bv.z; Bs[0][lk4+3][lm]=bv.w;
    __syncthreads();

    const int nk = K >> 3;
    for (int kt = 0; kt < nk; kt++){
        const int cur = kt & 1;
        if (kt + 1 < nk){
            av = mval ? *(const float4*)(Ap + (kt+1)*8) : make_float4(0,0,0,0);
            bv = *(const float4*)(Bp + (kt+1)*8);
        }
        #pragma unroll
        for (int k = 0; k < 8; k++){
            float4 a0 = *(const float4*)&As[cur][k][ty*8];
            float4 a1 = *(const float4*)&As[cur][k][ty*8+4];
            float4 b0 = *(const float4*)&Bs[cur][k][tx*8];
            float4 b1 = *(const float4*)&Bs[cur][k][tx*8+4];
            float am[8] = {a0.x,a0.y,a0.z,a0.w,a1.x,a1.y,a1.z,a1.w};
            float bn[8] = {b0.x,b0.y,b0.z,b0.w,b1.x,b1.y,b1.z,b1.w};
            #pragma unroll
            for (int i = 0; i < 8; i++)
                #pragma unroll
                for (int j = 0; j < 8; j++) cr[i][j] += am[i]*bn[j];
        }
        if (kt + 1 < nk){
            const int nxt = cur ^ 1;
            As[nxt][lk4+0][lm]=av.x; As[nxt][lk4+1][lm]=av.y; As[nxt][lk4+2][lm]=av.z; As[nxt][lk4+3][lm]=av.w;
            Bs[nxt][lk4+0][lm]=bv.x; Bs[nxt][lk4+1][lm]=bv.y; Bs[nxt][lk4+2][lm]=bv.z; Bs[nxt][lk4+3][lm]=bv.w;
        }
        __syncthreads();
    }

    #pragma unroll
    for (int i = 0; i < 8; i++){
        int m = m0 + ty*8 + i;
        if (m >= M) continue;
        size_t rb = (mode == 1) ? (size_t)(m & 15) * 4064000 + (size_t)(m >> 4) * 32000
                                : (size_t)m * ldc;
        #pragma unroll
        for (int j4 = 0; j4 < 8; j4 += 4){
            int n = n0 + tx*8 + j4;
            float vv[4];
            #pragma unroll
            for (int j = 0; j < 4; j++){
                float x = cr[i][j4+j];
                if (bias)   x += bias[n + j];
                if (bias2d) x += bias2d[(size_t)(m & 15)*2048 + n + j];
                if (act)    x = tanha(x);
                vv[j] = x;
            }
            *(float4*)(C + rb + n) = make_float4(vv[0], vv[1], vv[2], vv[3]);
        }
    }
}

// ---------------- persistent encoder: 128 steps in one kernel ----------------
// grid 128 x 256 threads. Per step: R7 k_encstep body (p = blk*256+tid), then grid barrier.
__global__ __launch_bounds__(256) void k_encoder(
    const float* __restrict__ Whh_f, const float* __restrict__ Whh_b)
{
    const unsigned NBLK = 128;
    int p = blockIdx.x*256 + threadIdx.x;   // 32768
    int half = p & 1;
    int pair = p >> 1;
    int dir  = pair >> 13;                  // 0 fwd, 1 bwd
    int rem  = pair & 8191;
    int b = rem & 15;
    int d = rem >> 4;
    const float* Whh = dir ? Whh_b : Whh_f;
    int klo = half * 256;
    const float4* w0 = (const float4*)(Whh + (size_t)d*512 + klo);
    const float4* w1 = (const float4*)(Whh + (size_t)(d+512)*512 + klo);
    const float4* w2 = (const float4*)(Whh + (size_t)(d+1024)*512 + klo);
    const float4* w3 = (const float4*)(Whh + (size_t)(d+1536)*512 + klo);

    for (int s = 0; s < 128; s++){
        int t = dir ? (127 - s) : s;
        const float* hprev = (dir ? d_hb[s & 1] : d_hf[s & 1]) + b*512;
        const float4* hp = (const float4*)(hprev + klo);
        float a0=0.f,a1=0.f,a2=0.f,a3=0.f;
        #pragma unroll 8
        for (int k = 0; k < 64; k++){
            float4 x = hp[k]; float4 w;
            w=w0[k]; DOT4(a0,x,w);
            w=w1[k]; DOT4(a1,x,w);
            w=w2[k]; DOT4(a2,x,w);
            w=w3[k]; DOT4(a3,x,w);
        }
        const unsigned FULL = 0xffffffffu;
        a0 += __shfl_xor_sync(FULL, a0, 1);
        a1 += __shfl_xor_sync(FULL, a1, 1);
        a2 += __shfl_xor_sync(FULL, a2, 1);
        a3 += __shfl_xor_sync(FULL, a3, 1);
        if (half == 0){
            const float* xg = (dir ? d_xgb : d_xgf) + (size_t)(t*16 + b)*2048;
            float gi = xg[d]        + a0;
            float gf = xg[d + 512]  + a1;
            float gg = xg[d + 1024] + a2;
            float go = xg[d + 1536] + a3;
            float* cbuf = dir ? d_cb : d_cf;
            float c = cbuf[b*512 + d];
            c = sigm(gf)*c + sigm(gi)*tanha(gg);
            float h = sigm(go)*tanha(c);
            cbuf[b*512 + d] = c;
            (dir ? d_hb[(s+1)&1] : d_hf[(s+1)&1])[b*512 + d] = h;
            d_xenc[(size_t)(b*128 + t)*1024 + dir*512 + d] = h;
        }
        gbar(NBLK);
    }
}

// ---------------- bridge (R7) ----------------
__global__ void k_bridge(const float* __restrict__ W_bridge){
    int p = blockIdx.x*128 + threadIdx.x;   // 8192
    int b = p & 15, j = p >> 4;
    const float4* c0p = (const float4*)(d_cf + b*512);
    const float4* c1p = (const float4*)(d_cb + b*512);
    const float4* w0p = (const float4*)(W_bridge + (size_t)j*1024);
    const float4* w1p = (const float4*)(W_bridge + (size_t)j*1024 + 512);
    float acc = 0.f;
    #pragma unroll 8
    for (int k = 0; k < 128; k++){
        float4 x = c0p[k], w = w0p[k]; DOT4(acc,x,w);
        x = c1p[k]; w = w1p[k]; DOT4(acc,x,w);
    }
    d_cdec[b*512 + j] = acc;
    d_hdec[0][b*512 + j] = tanha(acc);
}

// ---------------- persistent decoder: 127 steps x 4 phases in one kernel ----------------
// grid 128 x 256 threads.
__global__ __launch_bounds__(256) void k_decoder(
    const float* __restrict__ Wih_d, const float* __restrict__ Whh_d,
    const float* __restrict__ W_trg, const float* __restrict__ b_trg,
    const float* __restrict__ w_att, const float* __restrict__ b_att)
{
    const unsigned NBLK = 128;
    __shared__ float s_q[512];
    __shared__ float s_w[512];
    __shared__ float s_sc[128];
    int blk = blockIdx.x, tid = threadIdx.x;

    for (int t = 0; t < 127; t++){
        // ---- phase 1: gates + state update (R7 mapping) ----
        {
            int p = blk*256 + tid;
            int q = p & 3;
            int pair = p >> 2;
            int b = pair & 15;
            int d = pair >> 4;
            float a0=0.f,a1=0.f,a2=0.f,a3=0.f;
            int lo = q*384, hi = lo + 384;
            int fhi = hi < 1024 ? hi : 1024;
            if (lo < fhi){
                const float4* xp = (const float4*)(d_feed + b*1024 + lo);
                const float4* w0 = (const float4*)(Wih_d + (size_t)d*2048        + 1024 + lo);
                const float4* w1 = (const float4*)(Wih_d + (size_t)(d+512)*2048  + 1024 + lo);
                const float4* w2 = (const float4*)(Wih_d + (size_t)(d+1024)*2048 + 1024 + lo);
                const float4* w3 = (const float4*)(Wih_d + (size_t)(d+1536)*2048 + 1024 + lo);
                int n4 = (fhi - lo) >> 2;
                #pragma unroll 4
                for (int k = 0; k < n4; k++){
                    float4 x = xp[k]; float4 w;
                    w=w0[k]; DOT4(a0,x,w);
                    w=w1[k]; DOT4(a1,x,w);
                    w=w2[k]; DOT4(a2,x,w);
                    w=w3[k]; DOT4(a3,x,w);
                }
            }
            int hlo = lo > 1024 ? lo : 1024;
            if (hlo < hi){
                int k0 = hlo - 1024;
                const float4* xp = (const float4*)(d_hdec[t & 1] + b*512 + k0);
                const float4* w0 = (const float4*)(Whh_d + (size_t)d*512        + k0);
                const float4* w1 = (const float4*)(Whh_d + (size_t)(d+512)*512  + k0);
                const float4* w2 = (const float4*)(Whh_d + (size_t)(d+1024)*512 + k0);
                const float4* w3 = (const float4*)(Whh_d + (size_t)(d+1536)*512 + k0);
                int n4 = (hi - hlo) >> 2;
                #pragma unroll 4
                for (int k = 0; k < n4; k++){
                    float4 x = xp[k]; float4 w;
                    w=w0[k]; DOT4(a0,x,w);
                    w=w1[k]; DOT4(a1,x,w);
                    w=w2[k]; DOT4(a2,x,w);
                    w=w3[k]; DOT4(a3,x,w);
                }
            }
            const unsigned FULL = 0xffffffffu;
            a0 += __shfl_xor_sync(FULL,a0,1); a0 += __shfl_xor_sync(FULL,a0,2);
            a1 += __shfl_xor_sync(FULL,a1,1); a1 += __shfl_xor_sync(FULL,a1,2);
            a2 += __shfl_xor_sync(FULL,a2,1); a2 += __shfl_xor_sync(FULL,a2,2);
            a3 += __shfl_xor_sync(FULL,a3,1); a3 += __shfl_xor_sync(FULL,a3,2);
            if (q == 0){
                const float* gb = d_gbase + (size_t)(t*16 + b)*2048;
                float gi = gb[d]        + a0;
                float gf = gb[d + 512]  + a1;
                float gg = gb[d + 1024] + a2;
                float go = gb[d + 1536] + a3;
                float c = d_cdec[b*512 + d];
                c = sigm(gf)*c + sigm(gi)*tanha(gg);
                float h = sigm(go)*tanha(c);
                d_cdec[b*512 + d] = c;
                d_hdec[(t+1)&1][b*512 + d] = h;
                d_hcall[(size_t)(t*16 + b)*1536 + d] = h;
            }
        }
        gbar(NBLK);

        // ---- phase 2: q = h @ W_trg^T + b_trg (8192 threads) ----
        if (blk < 32){
            int p = blk*256 + tid;
            int b = p & 15, j = p >> 4;
            const float4* hp = (const float4*)(d_hdec[(t+1)&1] + b*512);
            const float4* wp = (const float4*)(W_trg + (size_t)j*512);
            float acc = 0.f;
            #pragma unroll 8
            for (int k = 0; k < 128; k++){ float4 x = hp[k], w = wp[k]; DOT4(acc,x,w); }
            d_attq[b*512 + j] = acc + b_trg[j];
        }
        gbar(NBLK);

        // ---- phase 3: scores (R7 k_dec_scores) ----
        {
            int b = blk & 15, lc = blk >> 4;
            for (int i = tid; i < 512; i += 256){ s_q[i] = d_attq[b*512 + i]; s_w[i] = w_att[i]; }
            __syncthreads();
            int lsub = tid >> 4, lane = tid & 15;
            int l = lc*16 + lsub;
            const float* xk = d_xenck + (size_t)(b*128 + l)*512;
            float sum = 0.f;
            #pragma unroll 8
            for (int d = lane; d < 512; d += 16) sum += tanhx(xk[d] + s_q[d]) * s_w[d];
            #pragma unroll
            for (int o = 8; o; o >>= 1) sum += __shfl_xor_sync(0xffffffffu, sum, o);
            if (lane == 0) d_sraw[b*128 + l] = sum + b_att[0];
            __syncthreads();
        }
        gbar(NBLK);

        // ---- phase 4: softmax + ctx (64 blocks) ----
        if (blk < 64){
            int b = blk & 15, jc = blk >> 4;
            if (tid < 32){
                float v0 = d_sraw[b*128+tid],    v1 = d_sraw[b*128+tid+32];
                float v2 = d_sraw[b*128+tid+64], v3 = d_sraw[b*128+tid+96];
                float mx = fmaxf(fmaxf(v0,v1), fmaxf(v2,v3));
                #pragma unroll
                for (int o = 16; o; o >>= 1) mx = fmaxf(mx, __shfl_xor_sync(0xffffffffu, mx, o));
                float e0 = __expf(v0-mx), e1 = __expf(v1-mx), e2 = __expf(v2-mx), e3 = __expf(v3-mx);
                float s = e0+e1+e2+e3;
                #pragma unroll
                for (int o = 16; o; o >>= 1) s += __shfl_xor_sync(0xffffffffu, s, o);
                float inv = __fdividef(1.f, s);
                s_sc[tid] = e0*inv; s_sc[tid+32] = e1*inv; s_sc[tid+64] = e2*inv; s_sc[tid+96] = e3*inv;
            }
            __syncthreads();
            int j = jc*256 + tid;
            const float* xe = d_xenc + (size_t)b*128*1024;
            float a0 = 0.f;
            #pragma unroll 4
            for (int l = 0; l < 128; l++) a0 += s_sc[l] * xe[(size_t)l*1024 + j];
            d_feed[b*1024 + j] = a0;
            d_hcall[(size_t)(t*16 + b)*1536 + 512 + j] = a0;
            __syncthreads();
        }
        gbar(NBLK);
    }
}

// ---------------- host ----------------
extern "C" void kernel_launch(void* const* d_in, const int* in_sizes, int n_in,
                              void* d_out, int out_size){
    const int*   x_train  = (const int*)  d_in[0];
    const int*   y_train  = (const int*)  d_in[2];
    const float* word_emb = (const float*)d_in[3];
    const float* attr_emb = (const float*)d_in[4];
    const float* Wih_f    = (const float*)d_in[5];
    const float* Whh_f    = (const float*)d_in[6];
    const float* bih_f    = (const float*)d_in[7];
    const float* bhh_f    = (const float*)d_in[8];
    const float* Wih_b    = (const float*)d_in[9];
    const float* Whh_b    = (const float*)d_in[10];
    const float* bih_b    = (const float*)d_in[11];
    const float* bhh_b    = (const float*)d_in[12];
    const float* W_bridge = (const float*)d_in[13];
    const float* W_enc2k  = (const float*)d_in[14];
    const float* Wih_d    = (const float*)d_in[15];
    const float* Whh_d    = (const float*)d_in[16];
    const float* bih_d    = (const float*)d_in[17];
    const float* bhh_d    = (const float*)d_in[18];
    const float* W_trg    = (const float*)d_in[19];
    const float* b_trg    = (const float*)d_in[20];
    const float* w_att    = (const float*)d_in[21];
    const float* b_att    = (const float*)d_in[22];
    const float* W_ro     = (const float*)d_in[23];
    const float* W_read   = (const float*)d_in[24];
    float* out = (float*)d_out;

    float *emb, *xgf, *xgb, *xenc, *xenck, *gbase, *abase, *hcall, *pres, *biasF, *biasB;
    cudaGetSymbolAddress((void**)&emb,   d_emb);
    cudaGetSymbolAddress((void**)&xgf,   d_xgf);
    cudaGetSymbolAddress((void**)&xgb,   d_xgb);
    cudaGetSymbolAddress((void**)&xenc,  d_xenc);
    cudaGetSymbolAddress((void**)&xenck, d_xenck);
    cudaGetSymbolAddress((void**)&gbase, d_gbase);
    cudaGetSymbolAddress((void**)&abase, d_abase);
    cudaGetSymbolAddress((void**)&hcall, d_hcall);
    cudaGetSymbolAddress((void**)&pres,  d_pres);
    cudaGetSymbolAddress((void**)&biasF, d_biasF);
    cudaGetSymbolAddress((void**)&biasB, d_biasB);

    // prep (launch #6 = clean mode-0 SGEMM for profiling)
    k_init <<<64, 256>>>();
    k_bias <<<8, 256>>>(bih_f, bhh_f, bih_b, bhh_b);
    k_embed<<<2048, 128>>>(x_train, word_emb);
    k_attr <<<16, 128>>>(y_train, attr_emb);
    k_gemm<<<dim3(16,16),256>>>(emb,512, Wih_f,512, xgf,2048, 2048,512, biasF,0, 0,0);
    k_gemm<<<dim3(16,16),256>>>(emb,512, Wih_b,512, xgb,2048, 2048,512, biasB,0, 0,0);

    // persistent encoder (128 steps, 1 launch)
    k_encoder<<<128,256>>>(Whh_f, Whh_b);

    // bridge + x_enc_k + decoder gate-base precompute
    k_bridge<<<64,128>>>(W_bridge);
    k_gemm<<<dim3(4,16),256>>>(xenc,1024, W_enc2k,1024, xenck,512, 2048,1024, 0,0, 0,0);
    k_abase<<<256,128>>>(Wih_d, bih_d, bhh_d);
    k_gemm<<<dim3(16,16),256>>>(emb,512, Wih_d,2048, gbase,2048, 2032,512, 0,abase, 0,0);

    // persistent decoder (127 steps x 4 phases, 1 launch)
    k_decoder<<<128,256>>>(Wih_d, Whh_d, W_trg, b_trg, w_att, b_att);

    // pre = tanh([h,ctx] @ W_ro^T), then logits = pre @ W_read^T -> out[b][t][v]
    k_gemm<<<dim3(4,16),256>>>(hcall,1536, W_ro,1536, pres,512, 2032,1536, 0,0, 1,0);
    k_gemm<<<dim3(250,16),256>>>(pres,512, W_read,512, out,0, 2032,512, 0,0, 0,1);
}

// round 13
// speedup vs baseline: 1.0413x; 1.0413x over previous
#include <cuda_runtime.h>
#include <cuda_bf16.h>
#include <math.h>

// ---------------- problem constants ----------------
// B=16, L=128, D=512, E=512, DI=2048, T=127, V=32000

// ---------------- scratch (device globals), R7 layouts ----------------
__device__ float d_emb  [2048*512];     // row m = l*16+b
__device__ float d_xgf  [2048*2048];    // [m=t*16+b][2048]
__device__ float d_xgb  [2048*2048];
__device__ float d_xenc [16*128*1024];  // [b][l][2D]
__device__ float d_xenck[16*128*512];   // [b][l][D]
__device__ float d_hf[2][16*512];       // [b][512]
__device__ float d_hb[2][16*512];
__device__ float d_cf[16*512];
__device__ float d_cb[16*512];
__device__ float d_biasF[2048];
__device__ float d_biasB[2048];
__device__ float d_attr [16*512];
__device__ float d_abase[16*2048];
__device__ float d_gbase[2032*2048];    // [m=t*16+b][2048]
__device__ float d_hdec[2][16*512];
__device__ float d_cdec[16*512];
__device__ float d_feed [16*1024];
__device__ float d_attq [16*512];
__device__ float d_sraw [16*128];
__device__ float d_hcall[2032*1536];    // [m][h512, ctx1024]
__device__ float d_pres [2032*512];

// ---------------- low-contention barriers (replay-safe) ----------------
__device__ unsigned g_sub[8];               // 16 arrivals each
__device__ unsigned g_root;                 // 8 arrivals
__device__ volatile unsigned g_gen;
__device__ unsigned g_bcnt[16];             // per-batch, 8 arrivals
__device__ volatile unsigned g_bgen[16];

// global barrier over 128 blocks: two-level arrivals, volatile-load polling
__device__ __forceinline__ void gbar(){
    __syncthreads();
    if (threadIdx.x == 0){
        __threadfence();
        unsigned gen = g_gen;                       // snapshot before arrival
        int grp = blockIdx.x & 7;
        if (atomicAdd(&g_sub[grp], 1u) == 15u){
            atomicExch(&g_sub[grp], 0u);
            if (atomicAdd(&g_root, 1u) == 7u){
                atomicExch(&g_root, 0u);
                __threadfence();
                g_gen = gen + 1u;                   // release
            } else {
                while (g_gen == gen) {}
            }
        } else {
            while (g_gen == gen) {}
        }
        __threadfence();
    }
    __syncthreads();
}

// per-batch barrier over the 8 blocks sharing batch b
__device__ __forceinline__ void bbar(int b){
    __syncthreads();
    if (threadIdx.x == 0){
        __threadfence();
        unsigned gen = g_bgen[b];
        if (atomicAdd(&g_bcnt[b], 1u) == 7u){
            atomicExch(&g_bcnt[b], 0u);
            __threadfence();
            g_bgen[b] = gen + 1u;
        } else {
            while (g_bgen[b] == gen) {}
        }
        __threadfence();
    }
    __syncthreads();
}

// ---------------- math helpers ----------------
__device__ __forceinline__ float tanha(float x){            // accurate
    x = fminf(fmaxf(x, -15.f), 15.f);
    float e = __expf(2.f * x);
    return __fdividef(e - 1.f, e + 1.f);
}
__device__ __forceinline__ float sigm(float x){
    return __fdividef(1.f, 1.f + __expf(-x));
}
__device__ __forceinline__ float tanhx(float x){            // HW approx (scores only)
    float y; asm("tanh.approx.f32 %0, %1;" : "=f"(y) : "f"(x)); return y;
}
#define DOT4(a,x,w) (a) += (x).x*(w).x + (x).y*(w).y + (x).z*(w).z + (x).w*(w).w

// ---------------- prep kernels (R7) ----------------
__global__ void k_init(){
    int i = blockIdx.x*256 + threadIdx.x;
    if (i < 16*512){ d_hf[0][i]=0.f; d_hb[0][i]=0.f; d_cf[i]=0.f; d_cb[i]=0.f; }
    if (i < 16*1024) d_feed[i]=0.f;
}

__global__ void k_bias(const float* __restrict__ bihf, const float* __restrict__ bhhf,
                       const float* __restrict__ bihb, const float* __restrict__ bhhb){
    int i = blockIdx.x*256 + threadIdx.x;
    if (i < 2048){ d_biasF[i] = bihf[i] + bhhf[i]; d_biasB[i] = bihb[i] + bhhb[i]; }
}

__global__ void k_embed(const int* __restrict__ x_train, const float* __restrict__ word_emb){
    int m = blockIdx.x;                 // m = l*16+b
    int b = m & 15, l = m >> 4;
    int tok = x_train[b*128 + l];
    const float4* src = (const float4*)(word_emb + (size_t)tok*512);
    float4* dst = (float4*)(d_emb + (size_t)m*512);
    dst[threadIdx.x] = src[threadIdx.x];
}

__global__ void k_attr(const int* __restrict__ y_train, const float* __restrict__ attr_emb){
    int b = blockIdx.x;
    float4 s = make_float4(0.f,0.f,0.f,0.f);
    for (int j = 0; j < 2; j++){
        int tok = y_train[b*2 + j];
        float4 v = ((const float4*)(attr_emb + (size_t)tok*512))[threadIdx.x];
        s.x += v.x; s.y += v.y; s.z += v.z; s.w += v.w;
    }
    ((float4*)(d_attr + b*512))[threadIdx.x] = s;
}

__global__ void k_abase(const float* __restrict__ Wih_d,
                        const float* __restrict__ bih_d, const float* __restrict__ bhh_d){
    int p = blockIdx.x*128 + threadIdx.x;     // 32768
    int b = p & 15, n = p >> 4;
    const float4* xp = (const float4*)(d_attr + b*512);
    const float4* wp = (const float4*)(Wih_d + (size_t)n*2048 + 512);
    float acc = 0.f;
    #pragma unroll 8
    for (int k = 0; k < 128; k++){ float4 x = xp[k], w = wp[k]; DOT4(acc,x,w); }
    d_abase[b*2048 + n] = acc + bih_d[n] + bhh_d[n];
}

// ---------------- generic SGEMM (exact R7): C[m][n] = sum_k A[m][k]*B[n][k] ----------------
__global__ __launch_bounds__(256) void k_gemm(
    const float* __restrict__ A, int lda,
    const float* __restrict__ B, int ldb,
    float* __restrict__ C, int ldc,
    int M, int K,
    const float* __restrict__ bias,
    const float* __restrict__ bias2d,
    int act, int mode)
{
    __shared__ float As[2][8][132];
    __shared__ float Bs[2][8][132];
    const int tid = threadIdx.x;
    const int m0 = blockIdx.y * 128, n0 = blockIdx.x * 128;
    const int lm = tid >> 1, lk4 = (tid & 1) * 4;
    const bool mval = (m0 + lm) < M;
    const float* Ap = A + (size_t)(m0 + lm) * lda + lk4;
    const float* Bp = B + (size_t)(n0 + lm) * ldb + lk4;
    const int tx = tid & 15, ty = tid >> 4;

    float cr[8][8];
    #pragma unroll
    for (int i = 0; i < 8; i++)
        #pragma unroll
        for (int j = 0; j < 8; j++) cr[i][j] = 0.f;

    float4 av = mval ? *(const float4*)Ap : make_float4(0,0,0,0);
    float4 bv = *(const float4*)Bp;
    As[0][lk4+0][lm]=av.x; As[0][lk4+1][lm]=av.y; As[0][lk4+2][lm]=av.z; As[0][lk4+3][lm]=av.w;
    Bs[0][lk4+0][lm]=bv.x; Bs[0][lk4+1][lm]=bv.y; Bs[0][lk4+2][lm]=bv.z; Bs[0][lk4+3][lm]=bv.w;
    __syncthreads();

    const int nk = K >> 3;
    for (int kt = 0; kt < nk; kt++){
        const int cur = kt & 1;
        if (kt + 1 < nk){
            av = mval ? *(const float4*)(Ap + (kt+1)*8) : make_float4(0,0,0,0);
            bv = *(const float4*)(Bp + (kt+1)*8);
        }
        #pragma unroll
        for (int k = 0; k < 8; k++){
            float4 a0 = *(const float4*)&As[cur][k][ty*8];
            float4 a1 = *(const float4*)&As[cur][k][ty*8+4];
            float4 b0 = *(const float4*)&Bs[cur][k][tx*8];
            float4 b1 = *(const float4*)&Bs[cur][k][tx*8+4];
            float am[8] = {a0.x,a0.y,a0.z,a0.w,a1.x,a1.y,a1.z,a1.w};
            float bn[8] = {b0.x,b0.y,b0.z,b0.w,b1.x,b1.y,b1.z,b1.w};
            #pragma unroll
            for (int i = 0; i < 8; i++)
                #pragma unroll
                for (int j = 0; j < 8; j++) cr[i][j] += am[i]*bn[j];
        }
        if (kt + 1 < nk){
            const int nxt = cur ^ 1;
            As[nxt][lk4+0][lm]=av.x; As[nxt][lk4+1][lm]=av.y; As[nxt][lk4+2][lm]=av.z; As[nxt][lk4+3][lm]=av.w;
            Bs[nxt][lk4+0][lm]=bv.x; Bs[nxt][lk4+1][lm]=bv.y; Bs[nxt][lk4+2][lm]=bv.z; Bs[nxt][lk4+3][lm]=bv.w;
        }
        __syncthreads();
    }

    #pragma unroll
    for (int i = 0; i < 8; i++){
        int m = m0 + ty*8 + i;
        if (m >= M) continue;
        size_t rb = (mode == 1) ? (size_t)(m & 15) * 4064000 + (size_t)(m >> 4) * 32000
                                : (size_t)m * ldc;
        #pragma unroll
        for (int j4 = 0; j4 < 8; j4 += 4){
            int n = n0 + tx*8 + j4;
            float vv[4];
            #pragma unroll
            for (int j = 0; j < 4; j++){
                float x = cr[i][j4+j];
                if (bias)   x += bias[n + j];
                if (bias2d) x += bias2d[(size_t)(m & 15)*2048 + n + j];
                if (act)    x = tanha(x);
                vv[j] = x;
            }
            *(float4*)(C + rb + n) = make_float4(vv[0], vv[1], vv[2], vv[3]);
        }
    }
}

// ---------------- persistent encoder: 128 steps, 1 launch ----------------
__global__ __launch_bounds__(256) void k_encoder(
    const float* __restrict__ Whh_f, const float* __restrict__ Whh_b)
{
    int p = blockIdx.x*256 + threadIdx.x;   // 32768
    int half = p & 1;
    int pair = p >> 1;
    int dir  = pair >> 13;
    int rem  = pair & 8191;
    int b = rem & 15;
    int d = rem >> 4;
    const float* Whh = dir ? Whh_b : Whh_f;
    int klo = half * 256;
    const float4* w0 = (const float4*)(Whh + (size_t)d*512 + klo);
    const float4* w1 = (const float4*)(Whh + (size_t)(d+512)*512 + klo);
    const float4* w2 = (const float4*)(Whh + (size_t)(d+1024)*512 + klo);
    const float4* w3 = (const float4*)(Whh + (size_t)(d+1536)*512 + klo);

    for (int s = 0; s < 128; s++){
        int t = dir ? (127 - s) : s;
        const float* hprev = (dir ? d_hb[s & 1] : d_hf[s & 1]) + b*512;
        const float4* hp = (const float4*)(hprev + klo);
        float a0=0.f,a1=0.f,a2=0.f,a3=0.f;
        #pragma unroll 8
        for (int k = 0; k < 64; k++){
            float4 x = hp[k]; float4 w;
            w=w0[k]; DOT4(a0,x,w);
            w=w1[k]; DOT4(a1,x,w);
            w=w2[k]; DOT4(a2,x,w);
            w=w3[k]; DOT4(a3,x,w);
        }
        const unsigned FULL = 0xffffffffu;
        a0 += __shfl_xor_sync(FULL, a0, 1);
        a1 += __shfl_xor_sync(FULL, a1, 1);
        a2 += __shfl_xor_sync(FULL, a2, 1);
        a3 += __shfl_xor_sync(FULL, a3, 1);
        if (half == 0){
            const float* xg = (dir ? d_xgb : d_xgf) + (size_t)(t*16 + b)*2048;
            float gi = xg[d]        + a0;
            float gf = xg[d + 512]  + a1;
            float gg = xg[d + 1024] + a2;
            float go = xg[d + 1536] + a3;
            float* cbuf = dir ? d_cb : d_cf;
            float c = cbuf[b*512 + d];
            c = sigm(gf)*c + sigm(gi)*tanha(gg);
            float h = sigm(go)*tanha(c);
            cbuf[b*512 + d] = c;
            (dir ? d_hb[(s+1)&1] : d_hf[(s+1)&1])[b*512 + d] = h;
            d_xenc[(size_t)(b*128 + t)*1024 + dir*512 + d] = h;
        }
        gbar();
    }
}

// ---------------- bridge (R7) ----------------
__global__ void k_bridge(const float* __restrict__ W_bridge){
    int p = blockIdx.x*128 + threadIdx.x;   // 8192
    int b = p & 15, j = p >> 4;
    const float4* c0p = (const float4*)(d_cf + b*512);
    const float4* c1p = (const float4*)(d_cb + b*512);
    const float4* w0p = (const float4*)(W_bridge + (size_t)j*1024);
    const float4* w1p = (const float4*)(W_bridge + (size_t)j*1024 + 512);
    float acc = 0.f;
    #pragma unroll 8
    for (int k = 0; k < 128; k++){
        float4 x = c0p[k], w = w0p[k]; DOT4(acc,x,w);
        x = c1p[k]; w = w1p[k]; DOT4(acc,x,w);
    }
    d_cdec[b*512 + j] = acc;
    d_hdec[0][b*512 + j] = tanha(acc);
}

// ---------------- persistent decoder: 127 steps x 3 phases, 1 launch ----------------
__global__ __launch_bounds__(256) void k_decoder(
    const float* __restrict__ Wih_d, const float* __restrict__ Whh_d,
    const float* __restrict__ W_trg, const float* __restrict__ b_trg,
    const float* __restrict__ w_att, const float* __restrict__ b_att)
{
    __shared__ float s_q[512];
    __shared__ float s_w[512];
    __shared__ float s_sc[128];
    int blk = blockIdx.x, tid = threadIdx.x;
    int ab = blk & 15, lc = blk >> 4;           // attention mapping: batch, l-chunk

    // stage w_att once
    for (int i = tid; i < 512; i += 256) s_w[i] = w_att[i];
    float batt = b_att[0];
    __syncthreads();

    for (int t = 0; t < 127; t++){
        // ---- phase 1: gates + state update (R7 mapping) ----
        {
            int p = blk*256 + tid;
            int q = p & 3;
            int pair = p >> 2;
            int b = pair & 15;
            int d = pair >> 4;
            float a0=0.f,a1=0.f,a2=0.f,a3=0.f;
            int lo = q*384, hi = lo + 384;
            int fhi = hi < 1024 ? hi : 1024;
            if (lo < fhi){
                const float4* xp = (const float4*)(d_feed + b*1024 + lo);
                const float4* w0 = (const float4*)(Wih_d + (size_t)d*2048        + 1024 + lo);
                const float4* w1 = (const float4*)(Wih_d + (size_t)(d+512)*2048  + 1024 + lo);
                const float4* w2 = (const float4*)(Wih_d + (size_t)(d+1024)*2048 + 1024 + lo);
                const float4* w3 = (const float4*)(Wih_d + (size_t)(d+1536)*2048 + 1024 + lo);
                int n4 = (fhi - lo) >> 2;
                #pragma unroll 4
                for (int k = 0; k < n4; k++){
                    float4 x = xp[k]; float4 w;
                    w=w0[k]; DOT4(a0,x,w);
                    w=w1[k]; DOT4(a1,x,w);
                    w=w2[k]; DOT4(a2,x,w);
                    w=w3[k]; DOT4(a3,x,w);
                }
            }
            int hlo = lo > 1024 ? lo : 1024;
            if (hlo < hi){
                int k0 = hlo - 1024;
                const float4* xp = (const float4*)(d_hdec[t & 1] + b*512 + k0);
                const float4* w0 = (const float4*)(Whh_d + (size_t)d*512        + k0);
                const float4* w1 = (const float4*)(Whh_d + (size_t)(d+512)*512  + k0);
                const float4* w2 = (const float4*)(Whh_d + (size_t)(d+1024)*512 + k0);
                const float4* w3 = (const float4*)(Whh_d + (size_t)(d+1536)*512 + k0);
                int n4 = (hi - hlo) >> 2;
                #pragma unroll 4
                for (int k = 0; k < n4; k++){
                    float4 x = xp[k]; float4 w;
                    w=w0[k]; DOT4(a0,x,w);
                    w=w1[k]; DOT4(a1,x,w);
                    w=w2[k]; DOT4(a2,x,w);
                    w=w3[k]; DOT4(a3,x,w);
                }
            }
            const unsigned FULL = 0xffffffffu;
            a0 += __shfl_xor_sync(FULL,a0,1); a0 += __shfl_xor_sync(FULL,a0,2);
            a1 += __shfl_xor_sync(FULL,a1,1); a1 += __shfl_xor_sync(FULL,a1,2);
            a2 += __shfl_xor_sync(FULL,a2,1); a2 += __shfl_xor_sync(FULL,a2,2);
            a3 += __shfl_xor_sync(FULL,a3,1); a3 += __shfl_xor_sync(FULL,a3,2);
            if (q == 0){
                const float* gb = d_gbase + (size_t)(t*16 + b)*2048;
                float gi = gb[d]        + a0;
                float gf = gb[d + 512]  + a1;
                float gg = gb[d + 1024] + a2;
                float go = gb[d + 1536] + a3;
                float c = d_cdec[b*512 + d];
                c = sigm(gf)*c + sigm(gi)*tanha(gg);
                float h = sigm(go)*tanha(c);
                d_cdec[b*512 + d] = c;
                d_hdec[(t+1)&1][b*512 + d] = h;
                d_hcall[(size_t)(t*16 + b)*1536 + d] = h;
            }
        }
        gbar();

        // ---- phase 2: q = h @ W_trg^T + b_trg (32 blocks) ----
        if (blk < 32){
            int p = blk*256 + tid;
            int b = p & 15, j = p >> 4;
            const float4* hp = (const float4*)(d_hdec[(t+1)&1] + b*512);
            const float4* wp = (const float4*)(W_trg + (size_t)j*512);
            float acc = 0.f;
            #pragma unroll 8
            for (int k = 0; k < 128; k++){ float4 x = hp[k], w = wp[k]; DOT4(acc,x,w); }
            d_attq[b*512 + j] = acc + b_trg[j];
        }
        gbar();

        // ---- phase 3: scores + per-batch softmax + ctx ----
        {
            for (int i = tid; i < 512; i += 256) s_q[i] = d_attq[ab*512 + i];
            __syncthreads();
            int lsub = tid >> 4, lane = tid & 15;
            int l = lc*16 + lsub;
            const float* xk = d_xenck + (size_t)(ab*128 + l)*512;
            float sum = 0.f;
            #pragma unroll 8
            for (int d = lane; d < 512; d += 16) sum += tanhx(xk[d] + s_q[d]) * s_w[d];
            #pragma unroll
            for (int o = 8; o; o >>= 1) sum += __shfl_xor_sync(0xffffffffu, sum, o);
            if (lane == 0) d_sraw[ab*128 + l] = sum + batt;
        }
        bbar(ab);   // 8 blocks of batch ab have written all 128 scores
        {
            if (tid < 32){
                float v0 = d_sraw[ab*128+tid],    v1 = d_sraw[ab*128+tid+32];
                float v2 = d_sraw[ab*128+tid+64], v3 = d_sraw[ab*128+tid+96];
                float mx = fmaxf(fmaxf(v0,v1), fmaxf(v2,v3));
                #pragma unroll
                for (int o = 16; o; o >>= 1) mx = fmaxf(mx, __shfl_xor_sync(0xffffffffu, mx, o));
                float e0 = __expf(v0-mx), e1 = __expf(v1-mx), e2 = __expf(v2-mx), e3 = __expf(v3-mx);
                float s = e0+e1+e2+e3;
                #pragma unroll
                for (int o = 16; o; o >>= 1) s += __shfl_xor_sync(0xffffffffu, s, o);
                float inv = __fdividef(1.f, s);
                s_sc[tid] = e0*inv; s_sc[tid+32] = e1*inv; s_sc[tid+64] = e2*inv; s_sc[tid+96] = e3*inv;
            }
            __syncthreads();
            if (tid < 128){
                int j = lc*128 + tid;
                const float* xe = d_xenc + (size_t)ab*128*1024;
                float a0 = 0.f;
                #pragma unroll 4
                for (int l = 0; l < 128; l++) a0 += s_sc[l] * xe[(size_t)l*1024 + j];
                d_feed[ab*1024 + j] = a0;
                d_hcall[(size_t)(t*16 + ab)*1536 + 512 + j] = a0;
            }
        }
        gbar();
    }
}

// ---------------- host ----------------
extern "C" void kernel_launch(void* const* d_in, const int* in_sizes, int n_in,
                              void* d_out, int out_size){
    const int*   x_train  = (const int*)  d_in[0];
    const int*   y_train  = (const int*)  d_in[2];
    const float* word_emb = (const float*)d_in[3];
    const float* attr_emb = (const float*)d_in[4];
    const float* Wih_f    = (const float*)d_in[5];
    const float* Whh_f    = (const float*)d_in[6];
    const float* bih_f    = (const float*)d_in[7];
    const float* bhh_f    = (const float*)d_in[8];
    const float* Wih_b    = (const float*)d_in[9];
    const float* Whh_b    = (const float*)d_in[10];
    const float* bih_b    = (const float*)d_in[11];
    const float* bhh_b    = (const float*)d_in[12];
    const float* W_bridge = (const float*)d_in[13];
    const float* W_enc2k  = (const float*)d_in[14];
    const float* Wih_d    = (const float*)d_in[15];
    const float* Whh_d    = (const float*)d_in[16];
    const float* bih_d    = (const float*)d_in[17];
    const float* bhh_d    = (const float*)d_in[18];
    const float* W_trg    = (const float*)d_in[19];
    const float* b_trg    = (const float*)d_in[20];
    const float* w_att    = (const float*)d_in[21];
    const float* b_att    = (const float*)d_in[22];
    const float* W_ro     = (const float*)d_in[23];
    const float* W_read   = (const float*)d_in[24];
    float* out = (float*)d_out;

    float *emb, *xgf, *xgb, *xenc, *xenck, *gbase, *abase, *hcall, *pres, *biasF, *biasB;
    cudaGetSymbolAddress((void**)&emb,   d_emb);
    cudaGetSymbolAddress((void**)&xgf,   d_xgf);
    cudaGetSymbolAddress((void**)&xgb,   d_xgb);
    cudaGetSymbolAddress((void**)&xenc,  d_xenc);
    cudaGetSymbolAddress((void**)&xenck, d_xenck);
    cudaGetSymbolAddress((void**)&gbase, d_gbase);
    cudaGetSymbolAddress((void**)&abase, d_abase);
    cudaGetSymbolAddress((void**)&hcall, d_hcall);
    cudaGetSymbolAddress((void**)&pres,  d_pres);
    cudaGetSymbolAddress((void**)&biasF, d_biasF);
    cudaGetSymbolAddress((void**)&biasB, d_biasB);

    // prep (launch #4 = k_gemm for ncu)
    k_init <<<64, 256>>>();
    k_bias <<<8, 256>>>(bih_f, bhh_f, bih_b, bhh_b);
    k_embed<<<2048, 128>>>(x_train, word_emb);
    k_gemm<<<dim3(16,16),256>>>(emb,512, Wih_f,512, xgf,2048, 2048,512, biasF,0, 0,0);
    k_attr <<<16, 128>>>(y_train, attr_emb);
    k_gemm<<<dim3(16,16),256>>>(emb,512, Wih_b,512, xgb,2048, 2048,512, biasB,0, 0,0);

    // persistent encoder
    k_encoder<<<128,256>>>(Whh_f, Whh_b);

    // bridge + x_enc_k + decoder gate-base precompute
    k_bridge<<<64,128>>>(W_bridge);
    k_gemm<<<dim3(4,16),256>>>(xenc,1024, W_enc2k,1024, xenck,512, 2048,1024, 0,0, 0,0);
    k_abase<<<256,128>>>(Wih_d, bih_d, bhh_d);
    k_gemm<<<dim3(16,16),256>>>(emb,512, Wih_d,2048, gbase,2048, 2032,512, 0,abase, 0,0);

    // persistent decoder
    k_decoder<<<128,256>>>(Wih_d, Whh_d, W_trg, b_trg, w_att, b_att);

    // pre = tanh([h,ctx] @ W_ro^T), then logits = pre @ W_read^T -> out[b][t][v]
    k_gemm<<<dim3(4,16),256>>>(hcall,1536, W_ro,1536, pres,512, 2032,1536, 0,0, 1,0);
    k_gemm<<<dim3(250,16),256>>>(pres,512, W_read,512, out,0, 2032,512, 0,0, 0,1);
}

// round 14
// speedup vs baseline: 1.0424x; 1.0011x over previous
#include <cuda_runtime.h>
#include <cuda_bf16.h>
#include <math.h>

// ---------------- problem constants ----------------
// B=16, L=128, D=512, E=512, DI=2048, T=127, V=32000

// ---------------- scratch (device globals), R7 layouts ----------------
__device__ float d_emb  [2048*512];     // row m = l*16+b
__device__ float d_xgf  [2048*2048];    // [m=t*16+b][2048]
__device__ float d_xgb  [2048*2048];
__device__ float d_xenc [16*128*1024];  // [b][l][2D]
__device__ float d_xenck[16*128*512];   // [b][l][D]
__device__ float d_hf[2][16*512];       // [b][512]
__device__ float d_hb[2][16*512];
__device__ float d_cf[16*512];
__device__ float d_cb[16*512];
__device__ float d_biasF[2048];
__device__ float d_biasB[2048];
__device__ float d_attr [16*512];
__device__ float d_abase[16*2048];
__device__ float d_gbase[2032*2048];    // [m=t*16+b][2048]
__device__ float d_hdec[2][16*512];
__device__ float d_cdec[16*512];
__device__ float d_feed [16*1024];
__device__ float d_attq [16*512];
__device__ float d_sraw [16*128];
__device__ float d_hcall[2032*1536];    // [m][h512, ctx1024]
__device__ float d_pres [2032*512];

// ---------------- low-contention barriers (replay-safe) ----------------
__device__ unsigned g_sub[8];               // 16 arrivals each
__device__ unsigned g_root;                 // 8 arrivals
__device__ volatile unsigned g_gen;
__device__ unsigned g_bcnt[16];             // per-batch, 8 arrivals
__device__ volatile unsigned g_bgen[16];

// global barrier over 128 blocks: two-level arrivals, volatile-load polling
__device__ __forceinline__ void gbar(){
    __syncthreads();
    if (threadIdx.x == 0){
        __threadfence();
        unsigned gen = g_gen;                       // snapshot before arrival
        int grp = blockIdx.x & 7;
        if (atomicAdd(&g_sub[grp], 1u) == 15u){
            atomicExch(&g_sub[grp], 0u);
            if (atomicAdd(&g_root, 1u) == 7u){
                atomicExch(&g_root, 0u);
                __threadfence();
                g_gen = gen + 1u;                   // release
            } else {
                while (g_gen == gen) {}
            }
        } else {
            while (g_gen == gen) {}
        }
        __threadfence();
    }
    __syncthreads();
}

// per-batch barrier over the 8 blocks sharing batch b
__device__ __forceinline__ void bbar(int b){
    __syncthreads();
    if (threadIdx.x == 0){
        __threadfence();
        unsigned gen = g_bgen[b];
        if (atomicAdd(&g_bcnt[b], 1u) == 7u){
            atomicExch(&g_bcnt[b], 0u);
            __threadfence();
            g_bgen[b] = gen + 1u;
        } else {
            while (g_bgen[b] == gen) {}
        }
        __threadfence();
    }
    __syncthreads();
}

// ---------------- math helpers ----------------
__device__ __forceinline__ float tanha(float x){            // accurate
    x = fminf(fmaxf(x, -15.f), 15.f);
    float e = __expf(2.f * x);
    return __fdividef(e - 1.f, e + 1.f);
}
__device__ __forceinline__ float sigm(float x){
    return __fdividef(1.f, 1.f + __expf(-x));
}
__device__ __forceinline__ float tanhx(float x){            // HW approx (scores only)
    float y; asm("tanh.approx.f32 %0, %1;" : "=f"(y) : "f"(x)); return y;
}
#define DOT4(a,x,w) (a) += (x).x*(w).x + (x).y*(w).y + (x).z*(w).z + (x).w*(w).w

// ---------------- prep kernels (R7) ----------------
__global__ void k_init(){
    int i = blockIdx.x*256 + threadIdx.x;
    if (i < 16*512){ d_hf[0][i]=0.f; d_hb[0][i]=0.f; d_cf[i]=0.f; d_cb[i]=0.f; }
    if (i < 16*1024) d_feed[i]=0.f;
}

__global__ void k_bias(const float* __restrict__ bihf, const float* __restrict__ bhhf,
                       const float* __restrict__ bihb, const float* __restrict__ bhhb){
    int i = blockIdx.x*256 + threadIdx.x;
    if (i < 2048){ d_biasF[i] = bihf[i] + bhhf[i]; d_biasB[i] = bihb[i] + bhhb[i]; }
}

__global__ void k_embed(const int* __restrict__ x_train, const float* __restrict__ word_emb){
    int m = blockIdx.x;                 // m = l*16+b
    int b = m & 15, l = m >> 4;
    int tok = x_train[b*128 + l];
    const float4* src = (const float4*)(word_emb + (size_t)tok*512);
    float4* dst = (float4*)(d_emb + (size_t)m*512);
    dst[threadIdx.x] = src[threadIdx.x];
}

__global__ void k_attr(const int* __restrict__ y_train, const float* __restrict__ attr_emb){
    int b = blockIdx.x;
    float4 s = make_float4(0.f,0.f,0.f,0.f);
    for (int j = 0; j < 2; j++){
        int tok = y_train[b*2 + j];
        float4 v = ((const float4*)(attr_emb + (size_t)tok*512))[threadIdx.x];
        s.x += v.x; s.y += v.y; s.z += v.z; s.w += v.w;
    }
    ((float4*)(d_attr + b*512))[threadIdx.x] = s;
}

__global__ void k_abase(const float* __restrict__ Wih_d,
                        const float* __restrict__ bih_d, const float* __restrict__ bhh_d){
    int p = blockIdx.x*128 + threadIdx.x;     // 32768
    int b = p & 15, n = p >> 4;
    const float4* xp = (const float4*)(d_attr + b*512);
    const float4* wp = (const float4*)(Wih_d + (size_t)n*2048 + 512);
    float acc = 0.f;
    #pragma unroll 8
    for (int k = 0; k < 128; k++){ float4 x = xp[k], w = wp[k]; DOT4(acc,x,w); }
    d_abase[b*2048 + n] = acc + bih_d[n] + bhh_d[n];
}

// ---------------- generic SGEMM (exact R7): C[m][n] = sum_k A[m][k]*B[n][k] ----------------
__global__ __launch_bounds__(256) void k_gemm(
    const float* __restrict__ A, int lda,
    const float* __restrict__ B, int ldb,
    float* __restrict__ C, int ldc,
    int M, int K,
    const float* __restrict__ bias,
    const float* __restrict__ bias2d,
    int act, int mode)
{
    __shared__ float As[2][8][132];
    __shared__ float Bs[2][8][132];
    const int tid = threadIdx.x;
    const int m0 = blockIdx.y * 128, n0 = blockIdx.x * 128;
    const int lm = tid >> 1, lk4 = (tid & 1) * 4;
    const bool mval = (m0 + lm) < M;
    const float* Ap = A + (size_t)(m0 + lm) * lda + lk4;
    const float* Bp = B + (size_t)(n0 + lm) * ldb + lk4;
    const int tx = tid & 15, ty = tid >> 4;

    float cr[8][8];
    #pragma unroll
    for (int i = 0; i < 8; i++)
        #pragma unroll
        for (int j = 0; j < 8; j++) cr[i][j] = 0.f;

    float4 av = mval ? *(const float4*)Ap : make_float4(0,0,0,0);
    float4 bv = *(const float4*)Bp;
    As[0][lk4+0][lm]=av.x; As[0][lk4+1][lm]=av.y; As[0][lk4+2][lm]=av.z; As[0][lk4+3][lm]=av.w;
    Bs[0][lk4+0][lm]=bv.x; Bs[0][lk4+1][lm]=bv.y; Bs[0][lk4+2][lm]=bv.z; Bs[0][lk4+3][lm]=bv.w;
    __syncthreads();

    const int nk = K >> 3;
    for (int kt = 0; kt < nk; kt++){
        const int cur = kt & 1;
        if (kt + 1 < nk){
            av = mval ? *(const float4*)(Ap + (kt+1)*8) : make_float4(0,0,0,0);
            bv = *(const float4*)(Bp + (kt+1)*8);
        }
        #pragma unroll
        for (int k = 0; k < 8; k++){
            float4 a0 = *(const float4*)&As[cur][k][ty*8];
            float4 a1 = *(const float4*)&As[cur][k][ty*8+4];
            float4 b0 = *(const float4*)&Bs[cur][k][tx*8];
            float4 b1 = *(const float4*)&Bs[cur][k][tx*8+4];
            float am[8] = {a0.x,a0.y,a0.z,a0.w,a1.x,a1.y,a1.z,a1.w};
            float bn[8] = {b0.x,b0.y,b0.z,b0.w,b1.x,b1.y,b1.z,b1.w};
            #pragma unroll
            for (int i = 0; i < 8; i++)
                #pragma unroll
                for (int j = 0; j < 8; j++) cr[i][j] += am[i]*bn[j];
        }
        if (kt + 1 < nk){
            const int nxt = cur ^ 1;
            As[nxt][lk4+0][lm]=av.x; As[nxt][lk4+1][lm]=av.y; As[nxt][lk4+2][lm]=av.z; As[nxt][lk4+3][lm]=av.w;
            Bs[nxt][lk4+0][lm]=bv.x; Bs[nxt][lk4+1][lm]=bv.y; Bs[nxt][lk4+2][lm]=bv.z; Bs[nxt][lk4+3][lm]=bv.w;
        }
        __syncthreads();
    }

    #pragma unroll
    for (int i = 0; i < 8; i++){
        int m = m0 + ty*8 + i;
        if (m >= M) continue;
        size_t rb = (mode == 1) ? (size_t)(m & 15) * 4064000 + (size_t)(m >> 4) * 32000
                                : (size_t)m * ldc;
        #pragma unroll
        for (int j4 = 0; j4 < 8; j4 += 4){
            int n = n0 + tx*8 + j4;
            float vv[4];
            #pragma unroll
            for (int j = 0; j < 4; j++){
                float x = cr[i][j4+j];
                if (bias)   x += bias[n + j];
                if (bias2d) x += bias2d[(size_t)(m & 15)*2048 + n + j];
                if (act)    x = tanha(x);
                vv[j] = x;
            }
            *(float4*)(C + rb + n) = make_float4(vv[0], vv[1], vv[2], vv[3]);
        }
    }
}

// ---------------- persistent encoder: 128 steps, 1 launch ----------------
__global__ __launch_bounds__(256) void k_encoder(
    const float* __restrict__ Whh_f, const float* __restrict__ Whh_b)
{
    int p = blockIdx.x*256 + threadIdx.x;   // 32768
    int half = p & 1;
    int pair = p >> 1;
    int dir  = pair >> 13;
    int rem  = pair & 8191;
    int b = rem & 15;
    int d = rem >> 4;
    const float* Whh = dir ? Whh_b : Whh_f;
    int klo = half * 256;
    const float4* w0 = (const float4*)(Whh + (size_t)d*512 + klo);
    const float4* w1 = (const float4*)(Whh + (size_t)(d+512)*512 + klo);
    const float4* w2 = (const float4*)(Whh + (size_t)(d+1024)*512 + klo);
    const float4* w3 = (const float4*)(Whh + (size_t)(d+1536)*512 + klo);

    for (int s = 0; s < 128; s++){
        int t = dir ? (127 - s) : s;
        const float* hprev = (dir ? d_hb[s & 1] : d_hf[s & 1]) + b*512;
        const float4* hp = (const float4*)(hprev + klo);
        float a0=0.f,a1=0.f,a2=0.f,a3=0.f;
        #pragma unroll 8
        for (int k = 0; k < 64; k++){
            float4 x = hp[k]; float4 w;
            w=w0[k]; DOT4(a0,x,w);
            w=w1[k]; DOT4(a1,x,w);
            w=w2[k]; DOT4(a2,x,w);
            w=w3[k]; DOT4(a3,x,w);
        }
        const unsigned FULL = 0xffffffffu;
        a0 += __shfl_xor_sync(FULL, a0, 1);
        a1 += __shfl_xor_sync(FULL, a1, 1);
        a2 += __shfl_xor_sync(FULL, a2, 1);
        a3 += __shfl_xor_sync(FULL, a3, 1);
        if (half == 0){
            const float* xg = (dir ? d_xgb : d_xgf) + (size_t)(t*16 + b)*2048;
            float gi = xg[d]        + a0;
            float gf = xg[d + 512]  + a1;
            float gg = xg[d + 1024] + a2;
            float go = xg[d + 1536] + a3;
            float* cbuf = dir ? d_cb : d_cf;
            float c = cbuf[b*512 + d];
            c = sigm(gf)*c + sigm(gi)*tanha(gg);
            float h = sigm(go)*tanha(c);
            cbuf[b*512 + d] = c;
            (dir ? d_hb[(s+1)&1] : d_hf[(s+1)&1])[b*512 + d] = h;
            d_xenc[(size_t)(b*128 + t)*1024 + dir*512 + d] = h;
        }
        gbar();
    }
}

// ---------------- bridge (R7) ----------------
__global__ void k_bridge(const float* __restrict__ W_bridge){
    int p = blockIdx.x*128 + threadIdx.x;   // 8192
    int b = p & 15, j = p >> 4;
    const float4* c0p = (const float4*)(d_cf + b*512);
    const float4* c1p = (const float4*)(d_cb + b*512);
    const float4* w0p = (const float4*)(W_bridge + (size_t)j*1024);
    const float4* w1p = (const float4*)(W_bridge + (size_t)j*1024 + 512);
    float acc = 0.f;
    #pragma unroll 8
    for (int k = 0; k < 128; k++){
        float4 x = c0p[k], w = w0p[k]; DOT4(acc,x,w);
        x = c1p[k]; w = w1p[k]; DOT4(acc,x,w);
    }
    d_cdec[b*512 + j] = acc;
    d_hdec[0][b*512 + j] = tanha(acc);
}

// ---------------- persistent decoder: 127 steps x 3 phases, 1 launch ----------------
__global__ __launch_bounds__(256) void k_decoder(
    const float* __restrict__ Wih_d, const float* __restrict__ Whh_d,
    const float* __restrict__ W_trg, const float* __restrict__ b_trg,
    const float* __restrict__ w_att, const float* __restrict__ b_att)
{
    __shared__ float s_q[512];
    __shared__ float s_w[512];
    __shared__ float s_sc[128];
    int blk = blockIdx.x, tid = threadIdx.x;
    int ab = blk & 15, lc = blk >> 4;           // attention mapping: batch, l-chunk

    // stage w_att once
    for (int i = tid; i < 512; i += 256) s_w[i] = w_att[i];
    float batt = b_att[0];
    __syncthreads();

    for (int t = 0; t < 127; t++){
        // ---- phase 1: gates + state update (R7 mapping) ----
        {
            int p = blk*256 + tid;
            int q = p & 3;
            int pair = p >> 2;
            int b = pair & 15;
            int d = pair >> 4;
            float a0=0.f,a1=0.f,a2=0.f,a3=0.f;
            int lo = q*384, hi = lo + 384;
            int fhi = hi < 1024 ? hi : 1024;
            if (lo < fhi){
                const float4* xp = (const float4*)(d_feed + b*1024 + lo);
                const float4* w0 = (const float4*)(Wih_d + (size_t)d*2048        + 1024 + lo);
                const float4* w1 = (const float4*)(Wih_d + (size_t)(d+512)*2048  + 1024 + lo);
                const float4* w2 = (const float4*)(Wih_d + (size_t)(d+1024)*2048 + 1024 + lo);
                const float4* w3 = (const float4*)(Wih_d + (size_t)(d+1536)*2048 + 1024 + lo);
                int n4 = (fhi - lo) >> 2;
                #pragma unroll 4
                for (int k = 0; k < n4; k++){
                    float4 x = xp[k]; float4 w;
                    w=w0[k]; DOT4(a0,x,w);
                    w=w1[k]; DOT4(a1,x,w);
                    w=w2[k]; DOT4(a2,x,w);
                    w=w3[k]; DOT4(a3,x,w);
                }
            }
            int hlo = lo > 1024 ? lo : 1024;
            if (hlo < hi){
                int k0 = hlo - 1024;
                const float4* xp = (const float4*)(d_hdec[t & 1] + b*512 + k0);
                const float4* w0 = (const float4*)(Whh_d + (size_t)d*512        + k0);
                const float4* w1 = (const float4*)(Whh_d + (size_t)(d+512)*512  + k0);
                const float4* w2 = (const float4*)(Whh_d + (size_t)(d+1024)*512 + k0);
                const float4* w3 = (const float4*)(Whh_d + (size_t)(d+1536)*512 + k0);
                int n4 = (hi - hlo) >> 2;
                #pragma unroll 4
                for (int k = 0; k < n4; k++){
                    float4 x = xp[k]; float4 w;
                    w=w0[k]; DOT4(a0,x,w);
                    w=w1[k]; DOT4(a1,x,w);
                    w=w2[k]; DOT4(a2,x,w);
                    w=w3[k]; DOT4(a3,x,w);
                }
            }
            const unsigned FULL = 0xffffffffu;
            a0 += __shfl_xor_sync(FULL,a0,1); a0 += __shfl_xor_sync(FULL,a0,2);
            a1 += __shfl_xor_sync(FULL,a1,1); a1 += __shfl_xor_sync(FULL,a1,2);
            a2 += __shfl_xor_sync(FULL,a2,1); a2 += __shfl_xor_sync(FULL,a2,2);
            a3 += __shfl_xor_sync(FULL,a3,1); a3 += __shfl_xor_sync(FULL,a3,2);
            if (q == 0){
                const float* gb = d_gbase + (size_t)(t*16 + b)*2048;
                float gi = gb[d]        + a0;
                float gf = gb[d + 512]  + a1;
                float gg = gb[d + 1024] + a2;
                float go = gb[d + 1536] + a3;
                float c = d_cdec[b*512 + d];
                c = sigm(gf)*c + sigm(gi)*tanha(gg);
                float h = sigm(go)*tanha(c);
                d_cdec[b*512 + d] = c;
                d_hdec[(t+1)&1][b*512 + d] = h;
                d_hcall[(size_t)(t*16 + b)*1536 + d] = h;
            }
        }
        gbar();

        // ---- phase 2: q = h @ W_trg^T + b_trg (32 blocks) ----
        if (blk < 32){
            int p = blk*256 + tid;
            int b = p & 15, j = p >> 4;
            const float4* hp = (const float4*)(d_hdec[(t+1)&1] + b*512);
            const float4* wp = (const float4*)(W_trg + (size_t)j*512);
            float acc = 0.f;
            #pragma unroll 8
            for (int k = 0; k < 128; k++){ float4 x = hp[k], w = wp[k]; DOT4(acc,x,w); }
            d_attq[b*512 + j] = acc + b_trg[j];
        }
        gbar();

        // ---- phase 3: scores + per-batch softmax + ctx ----
        {
            for (int i = tid; i < 512; i += 256) s_q[i] = d_attq[ab*512 + i];
            __syncthreads();
            int lsub = tid >> 4, lane = tid & 15;
            int l = lc*16 + lsub;
            const float* xk = d_xenck + (size_t)(ab*128 + l)*512;
            float sum = 0.f;
            #pragma unroll 8
            for (int d = lane; d < 512; d += 16) sum += tanhx(xk[d] + s_q[d]) * s_w[d];
            #pragma unroll
            for (int o = 8; o; o >>= 1) sum += __shfl_xor_sync(0xffffffffu, sum, o);
            if (lane == 0) d_sraw[ab*128 + l] = sum + batt;
        }
        bbar(ab);   // 8 blocks of batch ab have written all 128 scores
        {
            if (tid < 32){
                float v0 = d_sraw[ab*128+tid],    v1 = d_sraw[ab*128+tid+32];
                float v2 = d_sraw[ab*128+tid+64], v3 = d_sraw[ab*128+tid+96];
                float mx = fmaxf(fmaxf(v0,v1), fmaxf(v2,v3));
                #pragma unroll
                for (int o = 16; o; o >>= 1) mx = fmaxf(mx, __shfl_xor_sync(0xffffffffu, mx, o));
                float e0 = __expf(v0-mx), e1 = __expf(v1-mx), e2 = __expf(v2-mx), e3 = __expf(v3-mx);
                float s = e0+e1+e2+e3;
                #pragma unroll
                for (int o = 16; o; o >>= 1) s += __shfl_xor_sync(0xffffffffu, s, o);
                float inv = __fdividef(1.f, s);
                s_sc[tid] = e0*inv; s_sc[tid+32] = e1*inv; s_sc[tid+64] = e2*inv; s_sc[tid+96] = e3*inv;
            }
            __syncthreads();
            if (tid < 128){
                int j = lc*128 + tid;
                const float* xe = d_xenc + (size_t)ab*128*1024;
                float a0 = 0.f;
                #pragma unroll 4
                for (int l = 0; l < 128; l++) a0 += s_sc[l] * xe[(size_t)l*1024 + j];
                d_feed[ab*1024 + j] = a0;
                d_hcall[(size_t)(t*16 + ab)*1536 + 512 + j] = a0;
            }
        }
        gbar();
    }
}

// ---------------- host ----------------
extern "C" void kernel_launch(void* const* d_in, const int* in_sizes, int n_in,
                              void* d_out, int out_size){
    const int*   x_train  = (const int*)  d_in[0];
    const int*   y_train  = (const int*)  d_in[2];
    const float* word_emb = (const float*)d_in[3];
    const float* attr_emb = (const float*)d_in[4];
    const float* Wih_f    = (const float*)d_in[5];
    const float* Whh_f    = (const float*)d_in[6];
    const float* bih_f    = (const float*)d_in[7];
    const float* bhh_f    = (const float*)d_in[8];
    const float* Wih_b    = (const float*)d_in[9];
    const float* Whh_b    = (const float*)d_in[10];
    const float* bih_b    = (const float*)d_in[11];
    const float* bhh_b    = (const float*)d_in[12];
    const float* W_bridge = (const float*)d_in[13];
    const float* W_enc2k  = (const float*)d_in[14];
    const float* Wih_d    = (const float*)d_in[15];
    const float* Whh_d    = (const float*)d_in[16];
    const float* bih_d    = (const float*)d_in[17];
    const float* bhh_d    = (const float*)d_in[18];
    const float* W_trg    = (const float*)d_in[19];
    const float* b_trg    = (const float*)d_in[20];
    const float* w_att    = (const float*)d_in[21];
    const float* b_att    = (const float*)d_in[22];
    const float* W_ro     = (const float*)d_in[23];
    const float* W_read   = (const float*)d_in[24];
    float* out = (float*)d_out;

    float *emb, *xgf, *xgb, *xenc, *xenck, *gbase, *abase, *hcall, *pres, *biasF, *biasB;
    cudaGetSymbolAddress((void**)&emb,   d_emb);
    cudaGetSymbolAddress((void**)&xgf,   d_xgf);
    cudaGetSymbolAddress((void**)&xgb,   d_xgb);
    cudaGetSymbolAddress((void**)&xenc,  d_xenc);
    cudaGetSymbolAddress((void**)&xenck, d_xenck);
    cudaGetSymbolAddress((void**)&gbase, d_gbase);
    cudaGetSymbolAddress((void**)&abase, d_abase);
    cudaGetSymbolAddress((void**)&hcall, d_hcall);
    cudaGetSymbolAddress((void**)&pres,  d_pres);
    cudaGetSymbolAddress((void**)&biasF, d_biasF);
    cudaGetSymbolAddress((void**)&biasB, d_biasB);

    // prep (launch #4 = k_gemm for ncu)
    k_init <<<64, 256>>>();
    k_bias <<<8, 256>>>(bih_f, bhh_f, bih_b, bhh_b);
    k_embed<<<2048, 128>>>(x_train, word_emb);
    k_gemm<<<dim3(16,16),256>>>(emb,512, Wih_f,512, xgf,2048, 2048,512, biasF,0, 0,0);
    k_attr <<<16, 128>>>(y_train, attr_emb);
    k_gemm<<<dim3(16,16),256>>>(emb,512, Wih_b,512, xgb,2048, 2048,512, biasB,0, 0,0);

    // persistent encoder
    k_encoder<<<128,256>>>(Whh_f, Whh_b);

    // bridge + x_enc_k + decoder gate-base precompute
    k_bridge<<<64,128>>>(W_bridge);
    k_gemm<<<dim3(4,16),256>>>(xenc,1024, W_enc2k,1024, xenck,512, 2048,1024, 0,0, 0,0);
    k_abase<<<256,128>>>(Wih_d, bih_d, bhh_d);
    k_gemm<<<dim3(16,16),256>>>(emb,512, Wih_d,2048, gbase,2048, 2032,512, 0,abase, 0,0);

    // persistent decoder
    k_decoder<<<128,256>>>(Wih_d, Whh_d, W_trg, b_trg, w_att, b_att);

    // pre = tanh([h,ctx] @ W_ro^T), then logits = pre @ W_read^T -> out[b][t][v]
    k_gemm<<<dim3(4,16),256>>>(hcall,1536, W_ro,1536, pres,512, 2032,1536, 0,0, 1,0);
    k_gemm<<<dim3(250,16),256>>>(pres,512, W_read,512, out,0, 2032,512, 0,0, 0,1);
}

// round 15
// speedup vs baseline: 1.2713x; 1.2196x over previous
#include <cuda_runtime.h>
#include <math.h>

// B=16, L=128, D=512, DI=2048, T=127, V=32000
__device__ float d_emb  [2048*512];
__device__ float d_xgf  [2048*2048];
__device__ float d_xgb  [2048*2048];
__device__ float d_xenc [16*128*1024];
__device__ float d_xenck[16*128*512];
__device__ float d_hf[2][16*512];
__device__ float d_hb[2][16*512];
__device__ float d_cf[16*512];
__device__ float d_cb[16*512];
__device__ float d_biasF[2048];
__device__ float d_biasB[2048];
__device__ float d_attr [16*512];
__device__ float d_abase[16*2048];
__device__ float d_gbase[2032*2048];
__device__ float d_hdec[2][16*512];
__device__ float d_cdec[16*512];
__device__ float d_feed [16*1024];
__device__ float d_attq [16*512];
__device__ float d_sraw [16*128];
__device__ float d_hcall[2032*1536];
__device__ float d_pres [2032*512];

__device__ __forceinline__ float tanha(float x){
    x = fminf(fmaxf(x, -15.f), 15.f);
    float e = __expf(2.f * x);
    return __fdividef(e - 1.f, e + 1.f);
}
__device__ __forceinline__ float sigm(float x){
    return __fdividef(1.f, 1.f + __expf(-x));
}
__device__ __forceinline__ float tanhx(float x){
    float y; asm("tanh.approx.f32 %0, %1;" : "=f"(y) : "f"(x)); return y;
}
#define DOT4(a,x,w) (a) += (x).x*(w).x + (x).y*(w).y + (x).z*(w).z + (x).w*(w).w

__global__ void k_init(){
    int i = blockIdx.x*256 + threadIdx.x;
    if (i < 16*512){ d_hf[0][i]=0.f; d_hb[0][i]=0.f; d_cf[i]=0.f; d_cb[i]=0.f; }
    if (i < 16*1024) d_feed[i]=0.f;
}
__global__ void k_bias(const float* __restrict__ bihf, const float* __restrict__ bhhf,
                       const float* __restrict__ bihb, const float* __restrict__ bhhb){
    int i = blockIdx.x*256 + threadIdx.x;
    if (i < 2048){ d_biasF[i] = bihf[i] + bhhf[i]; d_biasB[i] = bihb[i] + bhhb[i]; }
}
__global__ void k_embed(const int* __restrict__ x_train, const float* __restrict__ word_emb){
    int m = blockIdx.x;
    int b = m & 15, l = m >> 4;
    int tok = x_train[b*128 + l];
    ((float4*)(d_emb + (size_t)m*512))[threadIdx.x] =
        ((const float4*)(word_emb + (size_t)tok*512))[threadIdx.x];
}
__global__ void k_attr(const int* __restrict__ y_train, const float* __restrict__ attr_emb){
    int b = blockIdx.x;
    float4 s = make_float4(0.f,0.f,0.f,0.f);
    for (int j = 0; j < 2; j++){
        int tok = y_train[b*2 + j];
        float4 v = ((const float4*)(attr_emb + (size_t)tok*512))[threadIdx.x];
        s.x += v.x; s.y += v.y; s.z += v.z; s.w += v.w;
    }
    ((float4*)(d_attr + b*512))[threadIdx.x] = s;
}
__global__ void k_abase(const float* __restrict__ Wih_d,
                        const float* __restrict__ bih_d, const float* __restrict__ bhh_d){
    int p = blockIdx.x*128 + threadIdx.x;
    int b = p & 15, n = p >> 4;
    const float4* xp = (const float4*)(d_attr + b*512);
    const float4* wp = (const float4*)(Wih_d + (size_t)n*2048 + 512);
    float acc = 0.f;
    #pragma unroll 8
    for (int k = 0; k < 128; k++){ float4 x = xp[k], w = wp[k]; DOT4(acc,x,w); }
    d_abase[b*2048 + n] = acc + bih_d[n] + bhh_d[n];
}

// SGEMM (exact R7)
__global__ __launch_bounds__(256) void k_gemm(
    const float* __restrict__ A, int lda, const float* __restrict__ B, int ldb,
    float* __restrict__ C, int ldc, int M, int K,
    const float* __restrict__ bias, const float* __restrict__ bias2d, int act, int mode)
{
    __shared__ float As[2][8][132];
    __shared__ float Bs[2][8][132];
    const int tid = threadIdx.x;
    const int m0 = blockIdx.y * 128, n0 = blockIdx.x * 128;
    const int lm = tid >> 1, lk4 = (tid & 1) * 4;
    const bool mval = (m0 + lm) < M;
    const float* Ap = A + (size_t)(m0 + lm) * lda + lk4;
    const float* Bp = B + (size_t)(n0 + lm) * ldb + lk4;
    const int tx = tid & 15, ty = tid >> 4;
    float cr[8][8];
    #pragma unroll
    for (int i = 0; i < 8; i++)
        #pragma unroll
        for (int j = 0; j < 8; j++) cr[i][j] = 0.f;
    float4 av = mval ? *(const float4*)Ap : make_float4(0,0,0,0);
    float4 bv = *(const float4*)Bp;
    As[0][lk4+0][lm]=av.x; As[0][lk4+1][lm]=av.y; As[0][lk4+2][lm]=av.z; As[0][lk4+3][lm]=av.w;
    Bs[0][lk4+0][lm]=bv.x; Bs[0][lk4+1][lm]=bv.y; Bs[0][lk4+2][lm]=bv.z; Bs[0][lk4+3][lm]=bv.w;
    __syncthreads();
    const int nk = K >> 3;
    for (int kt = 0; kt < nk; kt++){
        const int cur = kt & 1;
        if (kt + 1 < nk){
            av = mval ? *(const float4*)(Ap + (kt+1)*8) : make_float4(0,0,0,0);
            bv = *(const float4*)(Bp + (kt+1)*8);
        }
        #pragma unroll
        for (int k = 0; k < 8; k++){
            float4 a0 = *(const float4*)&As[cur][k][ty*8];
            float4 a1 = *(const float4*)&As[cur][k][ty*8+4];
            float4 b0 = *(const float4*)&Bs[cur][k][tx*8];
            float4 b1 = *(const float4*)&Bs[cur][k][tx*8+4];
            float am[8] = {a0.x,a0.y,a0.z,a0.w,a1.x,a1.y,a1.z,a1.w};
            float bn[8] = {b0.x,b0.y,b0.z,b0.w,b1.x,b1.y,b1.z,b1.w};
            #pragma unroll
            for (int i = 0; i < 8; i++)
                #pragma unroll
                for (int j = 0; j < 8; j++) cr[i][j] += am[i]*bn[j];
        }
        if (kt + 1 < nk){
            const int nxt = cur ^ 1;
            As[nxt][lk4+0][lm]=av.x; As[nxt][lk4+1][lm]=av.y; As[nxt][lk4+2][lm]=av.z; As[nxt][lk4+3][lm]=av.w;
            Bs[nxt][lk4+0][lm]=bv.x; Bs[nxt][lk4+1][lm]=bv.y; Bs[nxt][lk4+2][lm]=bv.z; Bs[nxt][lk4+3][lm]=bv.w;
        }
        __syncthreads();
    }
    #pragma unroll
    for (int i = 0; i < 8; i++){
        int m = m0 + ty*8 + i;
        if (m >= M) continue;
        size_t rb = (mode == 1) ? (size_t)(m & 15) * 4064000 + (size_t)(m >> 4) * 32000
                                : (size_t)m * ldc;
        #pragma unroll
        for (int j4 = 0; j4 < 8; j4 += 4){
            int n = n0 + tx*8 + j4;
            float vv[4];
            #pragma unroll
            for (int j = 0; j < 4; j++){
                float x = cr[i][j4+j];
                if (bias)   x += bias[n + j];
                if (bias2d) x += bias2d[(size_t)(m & 15)*2048 + n + j];
                if (act)    x = tanha(x);
                vv[j] = x;
            }
            *(float4*)(C + rb + n) = make_float4(vv[0], vv[1], vv[2], vv[3]);
        }
    }
}

// encoder step: grid 128 x 256. h staged in smem (bank-staggered), weights LDG.
__global__ __launch_bounds__(256) void k_encstep(int s,
    const float* __restrict__ Whh_f, const float* __restrict__ Whh_b){
    __shared__ float4 hs4[16*130];   // [b]*130 + [half]*65 + r
    int tid = threadIdx.x;
    int p = blockIdx.x*256 + tid;
    int half = p & 1;
    int pair = p >> 1;
    int dir  = pair >> 13;           // constant per block
    int rem  = pair & 8191;
    int b = rem & 15;
    int d = rem >> 4;
    const float* hsrc = dir ? d_hb[s & 1] : d_hf[s & 1];
    const float4* src4 = (const float4*)hsrc;
    for (int i = tid; i < 2048; i += 256){
        int bb = i >> 7, r = i & 127, hh = r >> 6, rr = r & 63;
        hs4[bb*130 + hh*65 + rr] = src4[i];
    }
    __syncthreads();
    const float* Whh = dir ? Whh_b : Whh_f;
    int klo = half * 256;
    const float4* w0 = (const float4*)(Whh + (size_t)d*512 + klo);
    const float4* w1 = (const float4*)(Whh + (size_t)(d+512)*512 + klo);
    const float4* w2 = (const float4*)(Whh + (size_t)(d+1024)*512 + klo);
    const float4* w3 = (const float4*)(Whh + (size_t)(d+1536)*512 + klo);
    const float4* hp = hs4 + b*130 + half*65;
    float a0=0.f,a1=0.f,a2=0.f,a3=0.f;
    #pragma unroll 8
    for (int k = 0; k < 64; k++){
        float4 x = hp[k]; float4 w;
        w=w0[k]; DOT4(a0,x,w);
        w=w1[k]; DOT4(a1,x,w);
        w=w2[k]; DOT4(a2,x,w);
        w=w3[k]; DOT4(a3,x,w);
    }
    const unsigned FULL = 0xffffffffu;
    a0 += __shfl_xor_sync(FULL, a0, 1);
    a1 += __shfl_xor_sync(FULL, a1, 1);
    a2 += __shfl_xor_sync(FULL, a2, 1);
    a3 += __shfl_xor_sync(FULL, a3, 1);
    if (half == 0){
        int t = dir ? (127 - s) : s;
        const float* xg = (dir ? d_xgb : d_xgf) + (size_t)(t*16 + b)*2048;
        float gi = xg[d]        + a0;
        float gf = xg[d + 512]  + a1;
        float gg = xg[d + 1024] + a2;
        float go = xg[d + 1536] + a3;
        float* cbuf = dir ? d_cb : d_cf;
        float c = cbuf[b*512 + d];
        c = sigm(gf)*c + sigm(gi)*tanha(gg);
        float h = sigm(go)*tanha(c);
        cbuf[b*512 + d] = c;
        (dir ? d_hb[(s+1)&1] : d_hf[(s+1)&1])[b*512 + d] = h;
        d_xenc[(size_t)(b*128 + t)*1024 + dir*512 + d] = h;
    }
}

__global__ void k_bridge(const float* __restrict__ W_bridge){
    int p = blockIdx.x*128 + threadIdx.x;
    int b = p & 15, j = p >> 4;
    const float4* c0p = (const float4*)(d_cf + b*512);
    const float4* c1p = (const float4*)(d_cb + b*512);
    const float4* w0p = (const float4*)(W_bridge + (size_t)j*1024);
    const float4* w1p = (const float4*)(W_bridge + (size_t)j*1024 + 512);
    float acc = 0.f;
    #pragma unroll 8
    for (int k = 0; k < 128; k++){
        float4 x = c0p[k], w = w0p[k]; DOT4(acc,x,w);
        x = c1p[k]; w = w1p[k]; DOT4(acc,x,w);
    }
    d_cdec[b*512 + j] = acc;
    d_hdec[0][b*512 + j] = tanha(acc);
}

// decoder gates: grid 128 x 256, dyn smem 99328B: x=[feed|h] staged, staggered.
__global__ __launch_bounds__(256) void k_dec_gates(int t,
    const float* __restrict__ Wih_d, const float* __restrict__ Whh_d){
    extern __shared__ float4 xs4[];   // [b]*388 + [q]*97 + r
    int tid = threadIdx.x;
    const float4* feed4 = (const float4*)d_feed;
    const float4* h4 = (const float4*)d_hdec[t & 1];
    for (int i = tid; i < 6144; i += 256){
        int b = i / 384, r = i - b*384;
        int q = r / 96, rr = r - q*96;
        xs4[b*388 + q*97 + rr] = (r < 256) ? feed4[b*256 + r] : h4[b*128 + (r - 256)];
    }
    __syncthreads();
    int p = blockIdx.x*256 + tid;
    int q = p & 3;
    int pair = p >> 2;
    int b = pair & 15;
    int d = pair >> 4;
    float a0=0.f,a1=0.f,a2=0.f,a3=0.f;
    int lo = q*384, hi = lo + 384;
    int fhi = hi < 1024 ? hi : 1024;
    const float4* xp = xs4 + b*388 + q*97;
    int it = 0;
    if (lo < fhi){
        const float4* w0 = (const float4*)(Wih_d + (size_t)d*2048        + 1024 + lo);
        const float4* w1 = (const float4*)(Wih_d + (size_t)(d+512)*2048  + 1024 + lo);
        const float4* w2 = (const float4*)(Wih_d + (size_t)(d+1024)*2048 + 1024 + lo);
        const float4* w3 = (const float4*)(Wih_d + (size_t)(d+1536)*2048 + 1024 + lo);
        int n4 = (fhi - lo) >> 2;
        #pragma unroll 4
        for (int k = 0; k < n4; k++, it++){
            float4 x = xp[it]; float4 w;
            w=w0[k]; DOT4(a0,x,w);
            w=w1[k]; DOT4(a1,x,w);
            w=w2[k]; DOT4(a2,x,w);
            w=w3[k]; DOT4(a3,x,w);
        }
    }
    int hlo = lo > 1024 ? lo : 1024;
    if (hlo < hi){
        int k0 = hlo - 1024;
        const float4* w0 = (const float4*)(Whh_d + (size_t)d*512        + k0);
        const float4* w1 = (const float4*)(Whh_d + (size_t)(d+512)*512  + k0);
        const float4* w2 = (const float4*)(Whh_d + (size_t)(d+1024)*512 + k0);
        const float4* w3 = (const float4*)(Whh_d + (size_t)(d+1536)*512 + k0);
        int n4 = (hi - hlo) >> 2;
        #pragma unroll 4
        for (int k = 0; k < n4; k++, it++){
            float4 x = xp[it]; float4 w;
            w=w0[k]; DOT4(a0,x,w);
            w=w1[k]; DOT4(a1,x,w);
            w=w2[k]; DOT4(a2,x,w);
            w=w3[k]; DOT4(a3,x,w);
        }
    }
    const unsigned FULL = 0xffffffffu;
    a0 += __shfl_xor_sync(FULL,a0,1); a0 += __shfl_xor_sync(FULL,a0,2);
    a1 += __shfl_xor_sync(FULL,a1,1); a1 += __shfl_xor_sync(FULL,a1,2);
    a2 += __shfl_xor_sync(FULL,a2,1); a2 += __shfl_xor_sync(FULL,a2,2);
    a3 += __shfl_xor_sync(FULL,a3,1); a3 += __shfl_xor_sync(FULL,a3,2);
    if (q == 0){
        const float* gb = d_gbase + (size_t)(t*16 + b)*2048;
        float gi = gb[d]        + a0;
        float gf = gb[d + 512]  + a1;
        float gg = gb[d + 1024] + a2;
        float go = gb[d + 1536] + a3;
        float c = d_cdec[b*512 + d];
        c = sigm(gf)*c + sigm(gi)*tanha(gg);
        float h = sigm(go)*tanha(c);
        d_cdec[b*512 + d] = c;
        d_hdec[(t+1)&1][b*512 + d] = h;
        d_hcall[(size_t)(t*16 + b)*1536 + d] = h;
    }
}

__global__ void k_dec_q(int t, const float* __restrict__ W_trg, const float* __restrict__ b_trg){
    int p = blockIdx.x*128 + threadIdx.x;
    int b = p & 15, j = p >> 4;
    const float4* hp = (const float4*)(d_hdec[(t+1)&1] + b*512);
    const float4* wp = (const float4*)(W_trg + (size_t)j*512);
    float acc = 0.f;
    #pragma unroll 8
    for (int k = 0; k < 128; k++){ float4 x = hp[k], w = wp[k]; DOT4(acc,x,w); }
    d_attq[b*512 + j] = acc + b_trg[j];
}

__global__ void k_dec_scores(const float* __restrict__ w_att, const float* __restrict__ b_att){
    __shared__ float q_s[512];
    __shared__ float w_s[512];
    int b = blockIdx.x & 15, lc = blockIdx.x >> 4;
    int tid = threadIdx.x;
    for (int i = tid; i < 512; i += 256){ q_s[i] = d_attq[b*512 + i]; w_s[i] = w_att[i]; }
    __syncthreads();
    int lsub = tid >> 4, lane = tid & 15;
    int l = lc*16 + lsub;
    const float* xk = d_xenck + (size_t)(b*128 + l)*512;
    float sum = 0.f;
    #pragma unroll 8
    for (int d = lane; d < 512; d += 16) sum += tanhx(xk[d] + q_s[d]) * w_s[d];
    #pragma unroll
    for (int o = 8; o; o >>= 1) sum += __shfl_xor_sync(0xffffffffu, sum, o);
    if (lane == 0) d_sraw[b*128 + l] = sum + b_att[0];
}

__global__ void k_dec_ctx(int t){
    __shared__ float red[128];
    __shared__ float w_s[128];
    int b = blockIdx.x & 15, jc = blockIdx.x >> 4;
    int tid = threadIdx.x;
    float s = d_sraw[b*128 + tid];
    red[tid] = s; __syncthreads();
    #pragma unroll
    for (int o = 64; o; o >>= 1){ if (tid < o) red[tid] = fmaxf(red[tid], red[tid + o]); __syncthreads(); }
    float mx = red[0]; __syncthreads();
    float e = __expf(s - mx);
    red[tid] = e; __syncthreads();
    #pragma unroll
    for (int o = 64; o; o >>= 1){ if (tid < o) red[tid] += red[tid + o]; __syncthreads(); }
    float inv = __fdividef(1.f, red[0]);
    w_s[tid] = e * inv; __syncthreads();
    int j = jc*128 + tid;
    const float* xe = d_xenc + (size_t)b*128*1024 + j;
    float acc = 0.f;
    #pragma unroll 8
    for (int l = 0; l < 128; l++) acc += w_s[l] * xe[(size_t)l*1024];
    d_feed[b*1024 + j] = acc;
    d_hcall[(size_t)(t*16 + b)*1536 + 512 + j] = acc;
}

extern "C" void kernel_launch(void* const* d_in, const int* in_sizes, int n_in,
                              void* d_out, int out_size){
    const int*   x_train  = (const int*)  d_in[0];
    const int*   y_train  = (const int*)  d_in[2];
    const float* word_emb = (const float*)d_in[3];
    const float* attr_emb = (const float*)d_in[4];
    const float* Wih_f    = (const float*)d_in[5];
    const float* Whh_f    = (const float*)d_in[6];
    const float* bih_f    = (const float*)d_in[7];
    const float* bhh_f    = (const float*)d_in[8];
    const float* Wih_b    = (const float*)d_in[9];
    const float* Whh_b    = (const float*)d_in[10];
    const float* bih_b    = (const float*)d_in[11];
    const float* bhh_b    = (const float*)d_in[12];
    const float* W_bridge = (const float*)d_in[13];
    const float* W_enc2k  = (const float*)d_in[14];
    const float* Wih_d    = (const float*)d_in[15];
    const float* Whh_d    = (const float*)d_in[16];
    const float* bih_d    = (const float*)d_in[17];
    const float* bhh_d    = (const float*)d_in[18];
    const float* W_trg    = (const float*)d_in[19];
    const float* b_trg    = (const float*)d_in[20];
    const float* w_att    = (const float*)d_in[21];
    const float* b_att    = (const float*)d_in[22];
    const float* W_ro     = (const float*)d_in[23];
    const float* W_read   = (const float*)d_in[24];
    float* out = (float*)d_out;

    float *emb, *xgf, *xgb, *xenc, *xenck, *gbase, *abase, *hcall, *pres, *biasF, *biasB;
    cudaGetSymbolAddress((void**)&emb,   d_emb);
    cudaGetSymbolAddress((void**)&xgf,   d_xgf);
    cudaGetSymbolAddress((void**)&xgb,   d_xgb);
    cudaGetSymbolAddress((void**)&xenc,  d_xenc);
    cudaGetSymbolAddress((void**)&xenck, d_xenck);
    cudaGetSymbolAddress((void**)&gbase, d_gbase);
    cudaGetSymbolAddress((void**)&abase, d_abase);
    cudaGetSymbolAddress((void**)&hcall, d_hcall);
    cudaGetSymbolAddress((void**)&pres,  d_pres);
    cudaGetSymbolAddress((void**)&biasF, d_biasF);
    cudaGetSymbolAddress((void**)&biasB, d_biasB);

    cudaFuncSetAttribute(k_dec_gates, cudaFuncAttributeMaxDynamicSharedMemorySize, 99328);

    // launches 1-5, then #6 = first k_encstep (ncu -s 5 -c 1 target)
    k_init <<<64, 256>>>();
    k_bias <<<8, 256>>>(bih_f, bhh_f, bih_b, bhh_b);
    k_embed<<<2048, 128>>>(x_train, word_emb);
    k_gemm<<<dim3(16,16),256>>>(emb,512, Wih_f,512, xgf,2048, 2048,512, biasF,0, 0,0);
    k_gemm<<<dim3(16,16),256>>>(emb,512, Wih_b,512, xgb,2048, 2048,512, biasB,0, 0,0);

    for (int s = 0; s < 128; s++)
        k_encstep<<<128,256>>>(s, Whh_f, Whh_b);

    k_attr <<<16, 128>>>(y_train, attr_emb);
    k_bridge<<<64,128>>>(W_bridge);
    k_gemm<<<dim3(4,16),256>>>(xenc,1024, W_enc2k,1024, xenck,512, 2048,1024, 0,0, 0,0);
    k_abase<<<256,128>>>(Wih_d, bih_d, bhh_d);
    k_gemm<<<dim3(16,16),256>>>(emb,512, Wih_d,2048, gbase,2048, 2032,512, 0,abase, 0,0);

    for (int t = 0; t < 127; t++){
        k_dec_gates <<<128,256,99328>>>(t, Wih_d, Whh_d);
        k_dec_q     <<<64,128>>>(t, W_trg, b_trg);
        k_dec_scores<<<128,256>>>(w_att, b_att);
        k_dec_ctx   <<<128,128>>>(t);
    }

    k_gemm<<<dim3(4,16),256>>>(hcall,1536, W_ro,1536, pres,512, 2032,1536, 0,0, 1,0);
    k_gemm<<<dim3(250,16),256>>>(pres,512, W_read,512, out,0, 2032,512, 0,0, 0,1);
}